// round 15
// baseline (speedup 1.0000x reference)
#include <cuda_runtime.h>
#include <cuda_fp16.h>
#include <math.h>
#include <stdint.h>

#define N_NODES 50000
#define N_EDGES 600000
#define C_HID 128
#define C_OUT 64
#define N_GRAPHS 512
#define MT_PAD 3128     // 391*8 m-tiles of 16 rows
#define AGG_BLOCKS 6250 // 50000/8 warps
#define DEG_PAD 64      // padded CSR slot count (Poisson(12): P(deg>=64) ~ 1e-30)

// ---------------- scratch (__device__ globals) -------------------------------
__device__ __half   g_yh[N_NODES * 128];   // y (gathered operand), fp16
__device__ __half   g_zh[N_NODES * 128];   // z (self term), fp16
__device__ float    g_x2[N_NODES * 128];
__device__ uint32_t g_ah[MT_PAD * 8 * 128];  // A operand, fp16x2 fragments
__device__ uint32_t g_wh[5 * 8192];          // weights, fp16x2 fragments
__device__ int      g_fill[N_NODES];         // degree counters; zeroed at end of run
__device__ int      g_csrp[N_NODES * DEG_PAD];  // padded CSR
__device__ int      g_gstart[N_GRAPHS + 1];

// ---------------- padded CSR build (single pass) + gstart --------------------
__global__ void build_csr_kernel(const int* __restrict__ src, const int* __restrict__ dst,
                                 int* __restrict__ fill, int* __restrict__ csrp,
                                 const int* __restrict__ cluster, int* __restrict__ gstart) {
    int i = blockIdx.x * blockDim.x + threadIdx.x;
    if (i < N_EDGES) {
        int d = dst[i];
        int pos = atomicAdd(&fill[d], 1);
        if (pos < DEG_PAD) csrp[d * DEG_PAD + pos] = src[i];
    }
    if (i <= N_GRAPHS) {
        if (i == N_GRAPHS) gstart[i] = N_NODES;
        else {
            int lo = 0, hi = N_NODES;
            while (lo < hi) {
                int mid = (lo + hi) >> 1;
                if (cluster[mid] < i) lo = mid + 1; else hi = mid;
            }
            gstart[i] = lo;
        }
    }
}

// ---------------- fp16 pack helpers ------------------------------------------
__device__ __forceinline__ uint32_t pack_f16x2(float x, float y) {
    __half2 h = __floats2half2_rn(x, y);
    return *reinterpret_cast<uint32_t*>(&h);
}

// ---- combined packing: blocks [0,MT_PAD) pack A(x) fp16; rest pack weights --
__global__ void pack_all_kernel(const float* __restrict__ A,
                                const float* W0, const float* W1, const float* W2,
                                const float* W3, const float* W4, const float* W5,
                                uint32_t* __restrict__ Ah,
                                uint32_t* __restrict__ Wh) {
    int warp = threadIdx.x >> 5;
    int lane = threadIdx.x & 31;
    int gidl = lane >> 2, tig = lane & 3;

    if (blockIdx.x < MT_PAD) {
        int it = blockIdx.x * 8 + warp;
        int mt = it >> 3, kt = it & 7;
        uint32_t h[4];
#pragma unroll
        for (int r = 0; r < 4; r++) {
            int row = mt * 16 + gidl + (r & 1) * 8;
            int col = kt * 16 + tig * 2 + (r >> 1) * 8;
            float2 v = make_float2(0.f, 0.f);
            if (row < N_NODES) v = *reinterpret_cast<const float2*>(&A[row * 128 + col]);
            h[r] = pack_f16x2(v.x, v.y);
        }
        *reinterpret_cast<uint4*>(&Ah[(it * 32 + lane) * 4]) = make_uint4(h[0], h[1], h[2], h[3]);
        return;
    }

    int wit = (blockIdx.x - MT_PAD) * 8 + warp;
    if (wit >= 640) return;
    const float* W;
    int BNs, dst_mat, nt_off, tile;
    if (wit < 512) {
        int m = wit >> 7;
        tile = wit & 127;
        BNs = 128; dst_mat = m; nt_off = 0;
        W = (m == 0) ? W0 : (m == 1) ? W1 : (m == 2) ? W2 : W3;
    } else {
        int m = (wit - 512) >> 6;
        tile = (wit - 512) & 63;
        BNs = 64; dst_mat = 4; nt_off = m ? 8 : 0;
        W = m ? W5 : W4;
    }
    int NTs = BNs / 8;
    int kt = tile / NTs, nt = tile % NTs;
    int col = nt * 8 + gidl;
    uint32_t h[2];
#pragma unroll
    for (int r = 0; r < 2; r++) {
        int k = kt * 16 + tig * 2 + r * 8;
        float v0 = W[k * BNs + col];
        float v1 = W[(k + 1) * BNs + col];
        h[r] = pack_f16x2(v0, v1);
    }
    int didx = dst_mat * 8192 + (kt * 16 + nt + nt_off) * 64 + lane * 2;
    *reinterpret_cast<uint2*>(&Wh[didx]) = make_uint2(h[0], h[1]);
}

// ---------------- fp16 GEMM ---------------------------------------------------
__device__ __forceinline__ uint32_t smem_u32(const void* p) {
    uint32_t a;
    asm("{ .reg .u64 t; cvta.to.shared.u64 t, %1; cvt.u32.u64 %0, t; }" : "=r"(a) : "l"(p));
    return a;
}

__device__ __forceinline__ void cp16(uint32_t dst, const void* src) {
    asm volatile("cp.async.cg.shared.global [%0], [%1], 16;" :: "r"(dst), "l"(src) : "memory");
}

#define MMA_F16(c, a, b)                                                          \
    asm volatile(                                                                 \
        "mma.sync.aligned.m16n8k16.row.col.f32.f16.f16.f32 "                      \
        "{%0,%1,%2,%3},{%4,%5,%6,%7},{%8,%9},{%0,%1,%2,%3};"                      \
        : "+f"(c[0]), "+f"(c[1]), "+f"(c[2]), "+f"(c[3])                          \
        : "r"(a[0]), "r"(a[1]), "r"(a[2]), "r"(a[3]), "r"(b[0]), "r"(b[1]))

// C = A[M,128] @ W[128,128], pure fp16 operands, fp32 accumulate.
__global__ __launch_bounds__(256, 2) void f16_gemm(
    const uint32_t* __restrict__ Ah,
    const uint32_t* __restrict__ Bh0, const uint32_t* __restrict__ Bh1,
    __half* __restrict__ C0h, __half* __restrict__ C1h, int M) {
    constexpr int NT = 16;
    constexpr int STAGE = 8192 + 8192;
    extern __shared__ char smem[];

    const uint32_t* Bh = blockIdx.y ? Bh1 : Bh0;
    __half* C = blockIdx.y ? C1h : C0h;

    uint32_t sb = smem_u32(smem);
    int tid = threadIdx.x, lane = tid & 31, warp = tid >> 5;
    int wm = warp & 1, wn = warp >> 1;
    int bRow = blockIdx.x * 128;

    float acc[4][4][4];
#pragma unroll
    for (int mt = 0; mt < 4; mt++)
#pragma unroll
        for (int nt = 0; nt < 4; nt++)
#pragma unroll
            for (int j = 0; j < 4; j++) acc[mt][nt][j] = 0.f;

    auto load_stage = [&](int kc, int buf) {
#pragma unroll
        for (int i = 0; i < 2; i++) {   // A: 8KB
            int c = tid + i * 256;
            int t = c >> 5, o = (c & 31) * 16;
            int kt = t >> 3, mt = t & 7;
            const uint32_t* src = Ah + ((blockIdx.x * 8 + mt) * 8 + kc * 2 + kt) * 128;
            cp16(sb + buf * STAGE + t * 512 + o, (const char*)src + o);
        }
#pragma unroll
        for (int i = 0; i < 2; i++) {   // B: 8KB
            int c = tid + i * 256;
            int t = c >> 4, o = (c & 15) * 16;
            int kt = t >> 4;
            int nt = t & 15;
            const uint32_t* src = Bh + ((kc * 2 + kt) * NT + nt) * 64;
            cp16(sb + buf * STAGE + 8192 + t * 256 + o, (const char*)src + o);
        }
        asm volatile("cp.async.commit_group;" ::: "memory");
    };

    auto compute = [&](int buf) {
#pragma unroll
        for (int kt = 0; kt < 2; kt++) {
            uint32_t a[4][4];
#pragma unroll
            for (int mt = 0; mt < 4; mt++) {
                uint32_t ad = sb + buf * STAGE + (kt * 8 + (wm * 4 + mt)) * 512 + lane * 16;
                asm volatile("ld.shared.v4.b32 {%0,%1,%2,%3},[%4];"
                    : "=r"(a[mt][0]), "=r"(a[mt][1]), "=r"(a[mt][2]), "=r"(a[mt][3]) : "r"(ad));
            }
            uint32_t b[4][2];
#pragma unroll
            for (int nt = 0; nt < 4; nt++) {
                uint32_t ad = sb + buf * STAGE + 8192 +
                    (kt * NT + wn * 4 + nt) * 256 + lane * 8;
                asm volatile("ld.shared.v2.b32 {%0,%1},[%2];"
                    : "=r"(b[nt][0]), "=r"(b[nt][1]) : "r"(ad));
            }
#pragma unroll
            for (int mt = 0; mt < 4; mt++)
#pragma unroll
                for (int nt = 0; nt < 4; nt++)
                    MMA_F16(acc[mt][nt], a[mt], b[nt]);
        }
    };

    load_stage(0, 0);
    for (int kc = 0; kc < 4; kc++) {
        if (kc < 3) {
            load_stage(kc + 1, (kc + 1) & 1);
            asm volatile("cp.async.wait_group 1;" ::: "memory");
        } else {
            asm volatile("cp.async.wait_group 0;" ::: "memory");
        }
        __syncthreads();
        compute(kc & 1);
        __syncthreads();
    }

    int gid = lane >> 2, tig = lane & 3;
#pragma unroll
    for (int mt = 0; mt < 4; mt++) {
        int row = bRow + wm * 64 + mt * 16 + gid;
#pragma unroll
        for (int nt = 0; nt < 4; nt++) {
            int col = wn * 32 + nt * 8 + tig * 2;
            if (row < M)
                *reinterpret_cast<__half2*>(&C[row * 128 + col]) =
                    __floats2half2_rn(acc[mt][nt][0], acc[mt][nt][1]);
            if (row + 8 < M)
                *reinterpret_cast<__half2*>(&C[(row + 8) * 128 + col]) =
                    __floats2half2_rn(acc[mt][nt][2], acc[mt][nt][3]);
        }
    }
}

// ------- aggregation (fp16 gather, padded CSR) + fused fp16 fragment pack ----
__global__ void agg128_pack_kernel(const __half* __restrict__ yh, const __half* __restrict__ zh,
                                   const float* __restrict__ bl,
                                   const int* __restrict__ fill, const int* __restrict__ csrp,
                                   uint32_t* __restrict__ Ah,
                                   float* __restrict__ out_pre,
                                   float* __restrict__ out_f32) {
    int node = blockIdx.x * 8 + (threadIdx.x >> 5);
    if (node >= N_NODES) return;
    int lane = threadIdx.x & 31;

    int cnt = min(fill[node], DEG_PAD);
    const int* row = csrp + node * DEG_PAD;
    float4 acc = make_float4(0.f, 0.f, 0.f, 0.f);
#pragma unroll 8
    for (int e = 0; e < cnt; e++) {
        int s = row[e];
        uint2 raw = *reinterpret_cast<const uint2*>(&yh[s * 128 + lane * 4]);
        __half2 p0 = *reinterpret_cast<__half2*>(&raw.x);
        __half2 p1 = *reinterpret_cast<__half2*>(&raw.y);
        float2 f0 = __half22float2(p0);
        float2 f1 = __half22float2(p1);
        acc.x += f0.x; acc.y += f0.y; acc.z += f1.x; acc.w += f1.y;
    }
    float inv = 1.f / (float)max(cnt, 1);
    float4 b = *reinterpret_cast<const float4*>(&bl[lane * 4]);
    uint2 zraw = *reinterpret_cast<const uint2*>(&zh[node * 128 + lane * 4]);
    float2 z0 = __half22float2(*reinterpret_cast<__half2*>(&zraw.x));
    float2 z1 = __half22float2(*reinterpret_cast<__half2*>(&zraw.y));
    float4 h;
    h.x = acc.x * inv + b.x + z0.x;
    h.y = acc.y * inv + b.y + z0.y;
    h.z = acc.z * inv + b.z + z1.x;
    h.w = acc.w * inv + b.w + z1.y;
    if (out_pre) *reinterpret_cast<float4*>(&out_pre[node * 128 + lane * 4]) = h;
    float4 r = make_float4(fmaxf(h.x, 0.f), fmaxf(h.y, 0.f), fmaxf(h.z, 0.f), fmaxf(h.w, 0.f));
    if (out_f32) *reinterpret_cast<float4*>(&out_f32[node * 128 + lane * 4]) = r;

    int mt = node >> 4, gid = node & 7, rowhalf = (node >> 3) & 1;
    int kt = lane >> 2;
    float v01[2] = {r.x, r.z};
    float v11[2] = {r.y, r.w};
#pragma unroll
    for (int p = 0; p < 2; p++) {
        int c = lane * 4 + 2 * p;
        int ct = c & 15;
        int tig = (ct & 7) >> 1;
        int colhalf = ct >> 3;
        int reg = rowhalf + 2 * colhalf;
        int idx = ((mt * 8 + kt) * 32 + gid * 4 + tig) * 4 + reg;
        __half2 hh = __floats2half2_rn(v01[p], v11[p]);
        Ah[idx] = *reinterpret_cast<uint32_t*>(&hh);
    }
}

// ------- final: lsm (blocks<AGG_BLOCKS) + pool (next 64) + scratch re-zero ---
__global__ void final_kernel(const __half* __restrict__ yzh,
                             const float* __restrict__ bl,
                             const int* __restrict__ fill, const int* __restrict__ csrp,
                             const float* __restrict__ x2,
                             const int* __restrict__ gstart,
                             float* __restrict__ out_lsm,
                             float* __restrict__ out_g,
                             int* __restrict__ fill_clear) {
    int lane = threadIdx.x & 31;
    int warp = threadIdx.x >> 5;

    if (blockIdx.x < AGG_BLOCKS) {
        int node = blockIdx.x * 8 + warp;
        if (node >= N_NODES) return;
        int cnt = min(fill[node], DEG_PAD);
        const int* row = csrp + node * DEG_PAD;
        float2 acc = make_float2(0.f, 0.f);
#pragma unroll 8
        for (int e = 0; e < cnt; e++) {
            int s = row[e];
            __half2 v = *reinterpret_cast<const __half2*>(&yzh[s * 128 + lane * 2]);
            float2 f = __half22float2(v);
            acc.x += f.x; acc.y += f.y;
        }
        float inv = 1.f / (float)max(cnt, 1);
        float2 b = *reinterpret_cast<const float2*>(&bl[lane * 2]);
        __half2 zv = *reinterpret_cast<const __half2*>(&yzh[node * 128 + 64 + lane * 2]);
        float2 zi = __half22float2(zv);
        float2 h;
        h.x = acc.x * inv + b.x + zi.x;
        h.y = acc.y * inv + b.y + zi.y;

        float m = fmaxf(h.x, h.y);
#pragma unroll
        for (int off = 16; off > 0; off >>= 1)
            m = fmaxf(m, __shfl_xor_sync(0xFFFFFFFFu, m, off));
        float s = expf(h.x - m) + expf(h.y - m);
#pragma unroll
        for (int off = 16; off > 0; off >>= 1)
            s += __shfl_xor_sync(0xFFFFFFFFu, s, off);
        float ls = logf(s);
        *reinterpret_cast<float2*>(&out_lsm[node * 64 + lane * 2]) =
            make_float2(h.x - m - ls, h.y - m - ls);

        // re-zero fill for next run (after its last read this run)
        if (lane == 0) fill_clear[node] = 0;
    } else {
        int g = (blockIdx.x - AGG_BLOCKS) * 8 + warp;
        if (g >= N_GRAPHS) return;
        int lo = gstart[g], hi = gstart[g + 1];
        float4 acc = make_float4(0.f, 0.f, 0.f, 0.f);
        for (int i = lo; i < hi; i++) {
            float4 v = *reinterpret_cast<const float4*>(&x2[i * 128 + lane * 4]);
            acc.x += v.x; acc.y += v.y; acc.z += v.z; acc.w += v.w;
        }
        float inv = 1.f / (float)max(hi - lo, 1);
        acc.x *= inv; acc.y *= inv; acc.z *= inv; acc.w *= inv;
        *reinterpret_cast<float4*>(&out_g[g * 128 + lane * 4]) = acc;
    }
}

// ---------------- launch -----------------------------------------------------
extern "C" void kernel_launch(void* const* d_in, const int* in_sizes, int n_in,
                              void* d_out, int out_size) {
    const float* x       = (const float*)d_in[0];
    const int*   ei      = (const int*)d_in[1];
    const int*   cluster = (const int*)d_in[2];
    const float* Wl0 = (const float*)d_in[3];
    const float* bl0 = (const float*)d_in[4];
    const float* Wr0 = (const float*)d_in[5];
    const float* Wl1 = (const float*)d_in[6];
    const float* bl1 = (const float*)d_in[7];
    const float* Wr1 = (const float*)d_in[8];
    const float* Wl2 = (const float*)d_in[9];
    const float* bl2 = (const float*)d_in[10];
    const float* Wr2 = (const float*)d_in[11];

    const int* src = ei;
    const int* dst = ei + N_EDGES;

    float* out = (float*)d_out;
    float* out_lsm = out;
    float* out_pre = out + N_NODES * C_OUT;
    float* out_g   = out + N_NODES * C_OUT + N_NODES * C_HID;

    __half *yh, *zh;
    float *x2;
    uint32_t *ah, *wh;
    int *fill, *csrp, *gstart;
    cudaGetSymbolAddress((void**)&yh, g_yh);
    cudaGetSymbolAddress((void**)&zh, g_zh);
    cudaGetSymbolAddress((void**)&x2, g_x2);
    cudaGetSymbolAddress((void**)&ah, g_ah);
    cudaGetSymbolAddress((void**)&wh, g_wh);
    cudaGetSymbolAddress((void**)&fill, g_fill);
    cudaGetSymbolAddress((void**)&csrp, g_csrp);
    cudaGetSymbolAddress((void**)&gstart, g_gstart);

    const int SMEM = 2 * (8192 + 8192);  // 32768
    cudaFuncSetAttribute(f16_gemm, cudaFuncAttributeMaxDynamicSharedMemorySize, SMEM);

    // ---- fork: one-pass padded CSR build on side stream (fill pre-zeroed) ----
    cudaStream_t sb;
    cudaStreamCreateWithFlags(&sb, cudaStreamNonBlocking);
    cudaEvent_t eFork, eJoin;
    cudaEventCreateWithFlags(&eFork, cudaEventDisableTiming);
    cudaEventCreateWithFlags(&eJoin, cudaEventDisableTiming);

    cudaEventRecord(eFork, 0);
    cudaStreamWaitEvent(sb, eFork, 0);
    const int EDGE_GRID = (N_EDGES + 255) / 256;
    build_csr_kernel<<<EDGE_GRID, 256, 0, sb>>>(src, dst, fill, csrp, cluster, gstart);
    cudaEventRecord(eJoin, sb);

    // main stream: combined pack + layer0 GEMM
    pack_all_kernel<<<MT_PAD + 80, 256>>>(x, Wl0, Wr0, Wl1, Wr1, Wl2, Wr2, ah, wh);

    dim3 gg(391, 2);
    f16_gemm<<<gg, 256, SMEM>>>(ah, wh + 0 * 8192, wh + 1 * 8192, yh, zh, N_NODES);

    cudaStreamWaitEvent(0, eJoin, 0);

    // ---- layer 0 aggregation ----
    agg128_pack_kernel<<<AGG_BLOCKS, 256>>>(yh, zh, bl0, fill, csrp, ah, nullptr, nullptr);

    // ---- layer 1 ----
    f16_gemm<<<gg, 256, SMEM>>>(ah, wh + 2 * 8192, wh + 3 * 8192, yh, zh, N_NODES);
    agg128_pack_kernel<<<AGG_BLOCKS, 256>>>(yh, zh, bl1, fill, csrp, ah, out_pre, x2);

    // ---- layer 2 fused GEMM ([Wl2|Wr2]) ----
    dim3 gg1(391, 1);
    f16_gemm<<<gg1, 256, SMEM>>>(ah, wh + 4 * 8192, wh + 4 * 8192, yh, nullptr, N_NODES);

    // ---- final: log-softmax agg + pooling + fill re-zero ----
    final_kernel<<<AGG_BLOCKS + 64, 256>>>(yh, bl2, fill, csrp, x2, gstart,
                                           out_lsm, out_g, fill);
}

// round 16
// speedup vs baseline: 1.3297x; 1.3297x over previous
#include <cuda_runtime.h>
#include <cuda_fp16.h>
#include <math.h>
#include <stdint.h>

#define N_NODES 50000
#define N_EDGES 600000
#define C_HID 128
#define C_OUT 64
#define N_GRAPHS 512
#define MT_PAD 3128     // 391*8 m-tiles of 16 rows
#define NCHUNK 196      // ceil(50000/256)
#define AGG_BLOCKS 6250 // 50000/8 warps

// ---------------- scratch (__device__ globals) -------------------------------
__device__ __half   g_yh[N_NODES * 128];   // y (gathered operand), fp16
__device__ __half   g_zh[N_NODES * 128];   // z (self term), fp16
__device__ float    g_x2[N_NODES * 128];
__device__ uint32_t g_ah[MT_PAD * 8 * 128];  // A operand, fp16x2 fragments
__device__ uint32_t g_wh[5 * 8192];          // weights, fp16x2 fragments
__device__ int      g_deg[N_NODES];      // zeroed at end of each run
__device__ int      g_fill[N_NODES];     // zeroed at end of each run
__device__ int      g_ptrL[N_NODES];
__device__ int      g_off[256];
__device__ int      g_part[256];
__device__ int      g_csr[N_EDGES];
__device__ int      g_gstart[N_GRAPHS + 1];

__device__ __forceinline__ int ptr_at(int i) {
    if (i >= N_NODES) return N_EDGES;
    return g_ptrL[i] + g_off[i >> 8];
}

// ---------------- CSR helpers -------------------------------------------------
__global__ void hist_gstart_kernel(const int* __restrict__ dst, int* __restrict__ deg,
                                   const int* __restrict__ cluster, int* __restrict__ gstart) {
    int i = blockIdx.x * blockDim.x + threadIdx.x;
    if (i < N_EDGES) atomicAdd(&deg[dst[i]], 1);
    if (i <= N_GRAPHS) {
        if (i == N_GRAPHS) gstart[i] = N_NODES;
        else {
            int lo = 0, hi = N_NODES;
            while (lo < hi) {
                int mid = (lo + hi) >> 1;
                if (cluster[mid] < i) lo = mid + 1; else hi = mid;
            }
            gstart[i] = lo;
        }
    }
}

__global__ void scan1_kernel(const int* __restrict__ deg, int* __restrict__ ptrL,
                             int* __restrict__ part) {
    __shared__ int s[256];
    int t = threadIdx.x;
    int i = blockIdx.x * 256 + t;
    int d = (i < N_NODES) ? deg[i] : 0;
    s[t] = d;
    __syncthreads();
#pragma unroll
    for (int off = 1; off < 256; off <<= 1) {
        int v = (t >= off) ? s[t - off] : 0;
        __syncthreads();
        s[t] += v;
        __syncthreads();
    }
    if (i < N_NODES) ptrL[i] = s[t] - d;
    if (t == 255) part[blockIdx.x] = s[255];
}

__global__ void scan2_kernel(const int* __restrict__ part, int* __restrict__ off) {
    __shared__ int s[256];
    int t = threadIdx.x;
    int v0 = (t < NCHUNK) ? part[t] : 0;
    s[t] = v0;
    __syncthreads();
#pragma unroll
    for (int off2 = 1; off2 < 256; off2 <<= 1) {
        int v = (t >= off2) ? s[t - off2] : 0;
        __syncthreads();
        s[t] += v;
        __syncthreads();
    }
    off[t] = s[t] - v0;
}

__global__ void fill_kernel(const int* __restrict__ src, const int* __restrict__ dst,
                            int* __restrict__ fill, int* __restrict__ csr) {
    int i = blockIdx.x * blockDim.x + threadIdx.x;
    if (i >= N_EDGES) return;
    int d = dst[i];
    int pos = g_ptrL[d] + g_off[d >> 8] + atomicAdd(&fill[d], 1);
    csr[pos] = src[i];
}

// ---------------- fp16 pack helpers ------------------------------------------
__device__ __forceinline__ uint32_t pack_f16x2(float x, float y) {
    __half2 h = __floats2half2_rn(x, y);
    return *reinterpret_cast<uint32_t*>(&h);
}

// ---- combined packing: blocks [0,MT_PAD) pack A(x) fp16; rest pack weights --
__global__ void pack_all_kernel(const float* __restrict__ A,
                                const float* W0, const float* W1, const float* W2,
                                const float* W3, const float* W4, const float* W5,
                                uint32_t* __restrict__ Ah,
                                uint32_t* __restrict__ Wh) {
    int warp = threadIdx.x >> 5;
    int lane = threadIdx.x & 31;
    int gidl = lane >> 2, tig = lane & 3;

    if (blockIdx.x < MT_PAD) {
        int it = blockIdx.x * 8 + warp;
        int mt = it >> 3, kt = it & 7;
        uint32_t h[4];
#pragma unroll
        for (int r = 0; r < 4; r++) {
            int row = mt * 16 + gidl + (r & 1) * 8;
            int col = kt * 16 + tig * 2 + (r >> 1) * 8;
            float2 v = make_float2(0.f, 0.f);
            if (row < N_NODES) v = *reinterpret_cast<const float2*>(&A[row * 128 + col]);
            h[r] = pack_f16x2(v.x, v.y);
        }
        *reinterpret_cast<uint4*>(&Ah[(it * 32 + lane) * 4]) = make_uint4(h[0], h[1], h[2], h[3]);
        return;
    }

    int wit = (blockIdx.x - MT_PAD) * 8 + warp;
    if (wit >= 640) return;
    const float* W;
    int BNs, dst_mat, nt_off, tile;
    if (wit < 512) {
        int m = wit >> 7;
        tile = wit & 127;
        BNs = 128; dst_mat = m; nt_off = 0;
        W = (m == 0) ? W0 : (m == 1) ? W1 : (m == 2) ? W2 : W3;
    } else {
        int m = (wit - 512) >> 6;
        tile = (wit - 512) & 63;
        BNs = 64; dst_mat = 4; nt_off = m ? 8 : 0;
        W = m ? W5 : W4;
    }
    int NTs = BNs / 8;
    int kt = tile / NTs, nt = tile % NTs;
    int col = nt * 8 + gidl;
    uint32_t h[2];
#pragma unroll
    for (int r = 0; r < 2; r++) {
        int k = kt * 16 + tig * 2 + r * 8;
        float v0 = W[k * BNs + col];
        float v1 = W[(k + 1) * BNs + col];
        h[r] = pack_f16x2(v0, v1);
    }
    int didx = dst_mat * 8192 + (kt * 16 + nt + nt_off) * 64 + lane * 2;
    *reinterpret_cast<uint2*>(&Wh[didx]) = make_uint2(h[0], h[1]);
}

// ---------------- fp16 GEMM ---------------------------------------------------
__device__ __forceinline__ uint32_t smem_u32(const void* p) {
    uint32_t a;
    asm("{ .reg .u64 t; cvta.to.shared.u64 t, %1; cvt.u32.u64 %0, t; }" : "=r"(a) : "l"(p));
    return a;
}

__device__ __forceinline__ void cp16(uint32_t dst, const void* src) {
    asm volatile("cp.async.cg.shared.global [%0], [%1], 16;" :: "r"(dst), "l"(src) : "memory");
}

#define MMA_F16(c, a, b)                                                          \
    asm volatile(                                                                 \
        "mma.sync.aligned.m16n8k16.row.col.f32.f16.f16.f32 "                      \
        "{%0,%1,%2,%3},{%4,%5,%6,%7},{%8,%9},{%0,%1,%2,%3};"                      \
        : "+f"(c[0]), "+f"(c[1]), "+f"(c[2]), "+f"(c[3])                          \
        : "r"(a[0]), "r"(a[1]), "r"(a[2]), "r"(a[3]), "r"(b[0]), "r"(b[1]))

// C = A[M,128] @ W[128,128], pure fp16 operands, fp32 accumulate.
__global__ __launch_bounds__(256, 2) void f16_gemm(
    const uint32_t* __restrict__ Ah,
    const uint32_t* __restrict__ Bh0, const uint32_t* __restrict__ Bh1,
    __half* __restrict__ C0h, __half* __restrict__ C1h, int M) {
    constexpr int NT = 16;
    constexpr int STAGE = 8192 + 8192;
    extern __shared__ char smem[];

    const uint32_t* Bh = blockIdx.y ? Bh1 : Bh0;
    __half* C = blockIdx.y ? C1h : C0h;

    uint32_t sb = smem_u32(smem);
    int tid = threadIdx.x, lane = tid & 31, warp = tid >> 5;
    int wm = warp & 1, wn = warp >> 1;
    int bRow = blockIdx.x * 128;

    float acc[4][4][4];
#pragma unroll
    for (int mt = 0; mt < 4; mt++)
#pragma unroll
        for (int nt = 0; nt < 4; nt++)
#pragma unroll
            for (int j = 0; j < 4; j++) acc[mt][nt][j] = 0.f;

    auto load_stage = [&](int kc, int buf) {
#pragma unroll
        for (int i = 0; i < 2; i++) {   // A: 8KB
            int c = tid + i * 256;
            int t = c >> 5, o = (c & 31) * 16;
            int kt = t >> 3, mt = t & 7;
            const uint32_t* src = Ah + ((blockIdx.x * 8 + mt) * 8 + kc * 2 + kt) * 128;
            cp16(sb + buf * STAGE + t * 512 + o, (const char*)src + o);
        }
#pragma unroll
        for (int i = 0; i < 2; i++) {   // B: 8KB
            int c = tid + i * 256;
            int t = c >> 4, o = (c & 15) * 16;
            int kt = t >> 4;
            int nt = t & 15;
            const uint32_t* src = Bh + ((kc * 2 + kt) * NT + nt) * 64;
            cp16(sb + buf * STAGE + 8192 + t * 256 + o, (const char*)src + o);
        }
        asm volatile("cp.async.commit_group;" ::: "memory");
    };

    auto compute = [&](int buf) {
#pragma unroll
        for (int kt = 0; kt < 2; kt++) {
            uint32_t a[4][4];
#pragma unroll
            for (int mt = 0; mt < 4; mt++) {
                uint32_t ad = sb + buf * STAGE + (kt * 8 + (wm * 4 + mt)) * 512 + lane * 16;
                asm volatile("ld.shared.v4.b32 {%0,%1,%2,%3},[%4];"
                    : "=r"(a[mt][0]), "=r"(a[mt][1]), "=r"(a[mt][2]), "=r"(a[mt][3]) : "r"(ad));
            }
            uint32_t b[4][2];
#pragma unroll
            for (int nt = 0; nt < 4; nt++) {
                uint32_t ad = sb + buf * STAGE + 8192 +
                    (kt * NT + wn * 4 + nt) * 256 + lane * 8;
                asm volatile("ld.shared.v2.b32 {%0,%1},[%2];"
                    : "=r"(b[nt][0]), "=r"(b[nt][1]) : "r"(ad));
            }
#pragma unroll
            for (int mt = 0; mt < 4; mt++)
#pragma unroll
                for (int nt = 0; nt < 4; nt++)
                    MMA_F16(acc[mt][nt], a[mt], b[nt]);
        }
    };

    load_stage(0, 0);
    for (int kc = 0; kc < 4; kc++) {
        if (kc < 3) {
            load_stage(kc + 1, (kc + 1) & 1);
            asm volatile("cp.async.wait_group 1;" ::: "memory");
        } else {
            asm volatile("cp.async.wait_group 0;" ::: "memory");
        }
        __syncthreads();
        compute(kc & 1);
        __syncthreads();
    }

    int gid = lane >> 2, tig = lane & 3;
#pragma unroll
    for (int mt = 0; mt < 4; mt++) {
        int row = bRow + wm * 64 + mt * 16 + gid;
#pragma unroll
        for (int nt = 0; nt < 4; nt++) {
            int col = wn * 32 + nt * 8 + tig * 2;
            if (row < M)
                *reinterpret_cast<__half2*>(&C[row * 128 + col]) =
                    __floats2half2_rn(acc[mt][nt][0], acc[mt][nt][1]);
            if (row + 8 < M)
                *reinterpret_cast<__half2*>(&C[(row + 8) * 128 + col]) =
                    __floats2half2_rn(acc[mt][nt][2], acc[mt][nt][3]);
        }
    }
}

// ------- aggregation: hadd2-pair accumulation, flush to fp32 every 8 edges ---
__global__ void agg128_pack_kernel(const __half* __restrict__ yh, const __half* __restrict__ zh,
                                   const float* __restrict__ bl,
                                   const int* __restrict__ csr,
                                   uint32_t* __restrict__ Ah,
                                   float* __restrict__ out_pre,
                                   float* __restrict__ out_f32) {
    int node = blockIdx.x * 8 + (threadIdx.x >> 5);
    if (node >= N_NODES) return;
    int lane = threadIdx.x & 31;

    int lo = ptr_at(node), hi = ptr_at(node + 1);
    float4 acc = make_float4(0.f, 0.f, 0.f, 0.f);
    const __half2 hz = __floats2half2_rn(0.f, 0.f);
    int e = lo;
    while (e < hi) {
        int stop = min(e + 8, hi);
        __half2 a0 = hz, a1 = hz;
#pragma unroll 8
        for (; e < stop; e++) {
            int s = csr[e];
            uint2 raw = *reinterpret_cast<const uint2*>(&yh[s * 128 + lane * 4]);
            a0 = __hadd2(a0, *reinterpret_cast<__half2*>(&raw.x));
            a1 = __hadd2(a1, *reinterpret_cast<__half2*>(&raw.y));
        }
        float2 f0 = __half22float2(a0);
        float2 f1 = __half22float2(a1);
        acc.x += f0.x; acc.y += f0.y; acc.z += f1.x; acc.w += f1.y;
    }
    float inv = 1.f / (float)max(hi - lo, 1);
    float4 b = *reinterpret_cast<const float4*>(&bl[lane * 4]);
    uint2 zraw = *reinterpret_cast<const uint2*>(&zh[node * 128 + lane * 4]);
    float2 z0 = __half22float2(*reinterpret_cast<__half2*>(&zraw.x));
    float2 z1 = __half22float2(*reinterpret_cast<__half2*>(&zraw.y));
    float4 h;
    h.x = acc.x * inv + b.x + z0.x;
    h.y = acc.y * inv + b.y + z0.y;
    h.z = acc.z * inv + b.z + z1.x;
    h.w = acc.w * inv + b.w + z1.y;
    if (out_pre) *reinterpret_cast<float4*>(&out_pre[node * 128 + lane * 4]) = h;
    float4 r = make_float4(fmaxf(h.x, 0.f), fmaxf(h.y, 0.f), fmaxf(h.z, 0.f), fmaxf(h.w, 0.f));
    if (out_f32) *reinterpret_cast<float4*>(&out_f32[node * 128 + lane * 4]) = r;

    int mt = node >> 4, gid = node & 7, rowhalf = (node >> 3) & 1;
    int kt = lane >> 2;
    float v01[2] = {r.x, r.z};
    float v11[2] = {r.y, r.w};
#pragma unroll
    for (int p = 0; p < 2; p++) {
        int c = lane * 4 + 2 * p;
        int ct = c & 15;
        int tig = (ct & 7) >> 1;
        int colhalf = ct >> 3;
        int reg = rowhalf + 2 * colhalf;
        int idx = ((mt * 8 + kt) * 32 + gid * 4 + tig) * 4 + reg;
        __half2 hh = __floats2half2_rn(v01[p], v11[p]);
        Ah[idx] = *reinterpret_cast<uint32_t*>(&hh);
    }
}

// ------- final: lsm (hadd2 gather) + pool + scratch re-zero ------------------
__global__ void final_kernel(const __half* __restrict__ yzh,
                             const float* __restrict__ bl,
                             const int* __restrict__ csr,
                             const float* __restrict__ x2,
                             const int* __restrict__ gstart,
                             float* __restrict__ out_lsm,
                             float* __restrict__ out_g) {
    int lane = threadIdx.x & 31;
    int warp = threadIdx.x >> 5;

    {
        int gtid = blockIdx.x * blockDim.x + threadIdx.x;
        if (gtid < N_NODES) { g_deg[gtid] = 0; g_fill[gtid] = 0; }
    }

    if (blockIdx.x < AGG_BLOCKS) {
        int node = blockIdx.x * 8 + warp;
        if (node >= N_NODES) return;
        int lo = ptr_at(node), hi = ptr_at(node + 1);
        float2 acc = make_float2(0.f, 0.f);
        const __half2 hz = __floats2half2_rn(0.f, 0.f);
        int e = lo;
        while (e < hi) {
            int stop = min(e + 8, hi);
            __half2 a0 = hz;
#pragma unroll 8
            for (; e < stop; e++) {
                int s = csr[e];
                a0 = __hadd2(a0, *reinterpret_cast<const __half2*>(&yzh[s * 128 + lane * 2]));
            }
            float2 f = __half22float2(a0);
            acc.x += f.x; acc.y += f.y;
        }
        float inv = 1.f / (float)max(hi - lo, 1);
        float2 b = *reinterpret_cast<const float2*>(&bl[lane * 2]);
        __half2 zv = *reinterpret_cast<const __half2*>(&yzh[node * 128 + 64 + lane * 2]);
        float2 zi = __half22float2(zv);
        float2 h;
        h.x = acc.x * inv + b.x + zi.x;
        h.y = acc.y * inv + b.y + zi.y;

        float m = fmaxf(h.x, h.y);
#pragma unroll
        for (int off = 16; off > 0; off >>= 1)
            m = fmaxf(m, __shfl_xor_sync(0xFFFFFFFFu, m, off));
        float s = expf(h.x - m) + expf(h.y - m);
#pragma unroll
        for (int off = 16; off > 0; off >>= 1)
            s += __shfl_xor_sync(0xFFFFFFFFu, s, off);
        float ls = logf(s);
        *reinterpret_cast<float2*>(&out_lsm[node * 64 + lane * 2]) =
            make_float2(h.x - m - ls, h.y - m - ls);
    } else {
        int g = (blockIdx.x - AGG_BLOCKS) * 8 + warp;
        if (g >= N_GRAPHS) return;
        int lo = gstart[g], hi = gstart[g + 1];
        float4 acc = make_float4(0.f, 0.f, 0.f, 0.f);
        for (int i = lo; i < hi; i++) {
            float4 v = *reinterpret_cast<const float4*>(&x2[i * 128 + lane * 4]);
            acc.x += v.x; acc.y += v.y; acc.z += v.z; acc.w += v.w;
        }
        float inv = 1.f / (float)max(hi - lo, 1);
        acc.x *= inv; acc.y *= inv; acc.z *= inv; acc.w *= inv;
        *reinterpret_cast<float4*>(&out_g[g * 128 + lane * 4]) = acc;
    }
}

// ---------------- launch -----------------------------------------------------
extern "C" void kernel_launch(void* const* d_in, const int* in_sizes, int n_in,
                              void* d_out, int out_size) {
    const float* x       = (const float*)d_in[0];
    const int*   ei      = (const int*)d_in[1];
    const int*   cluster = (const int*)d_in[2];
    const float* Wl0 = (const float*)d_in[3];
    const float* bl0 = (const float*)d_in[4];
    const float* Wr0 = (const float*)d_in[5];
    const float* Wl1 = (const float*)d_in[6];
    const float* bl1 = (const float*)d_in[7];
    const float* Wr1 = (const float*)d_in[8];
    const float* Wl2 = (const float*)d_in[9];
    const float* bl2 = (const float*)d_in[10];
    const float* Wr2 = (const float*)d_in[11];

    const int* src = ei;
    const int* dst = ei + N_EDGES;

    float* out = (float*)d_out;
    float* out_lsm = out;
    float* out_pre = out + N_NODES * C_OUT;
    float* out_g   = out + N_NODES * C_OUT + N_NODES * C_HID;

    __half *yh, *zh;
    float *x2;
    uint32_t *ah, *wh;
    int *deg, *fill, *csr, *gstart;
    cudaGetSymbolAddress((void**)&yh, g_yh);
    cudaGetSymbolAddress((void**)&zh, g_zh);
    cudaGetSymbolAddress((void**)&x2, g_x2);
    cudaGetSymbolAddress((void**)&ah, g_ah);
    cudaGetSymbolAddress((void**)&wh, g_wh);
    cudaGetSymbolAddress((void**)&deg, g_deg);
    cudaGetSymbolAddress((void**)&fill, g_fill);
    cudaGetSymbolAddress((void**)&csr, g_csr);
    cudaGetSymbolAddress((void**)&gstart, g_gstart);

    int *ptrL, *offp, *part;
    cudaGetSymbolAddress((void**)&ptrL, g_ptrL);
    cudaGetSymbolAddress((void**)&offp, g_off);
    cudaGetSymbolAddress((void**)&part, g_part);

    const int SMEM = 2 * (8192 + 8192);  // 32768
    cudaFuncSetAttribute(f16_gemm, cudaFuncAttributeMaxDynamicSharedMemorySize, SMEM);

    // ---- fork: CSR build on side stream (deg/fill pre-zeroed by prior run) ----
    cudaStream_t sb;
    cudaStreamCreateWithFlags(&sb, cudaStreamNonBlocking);
    cudaEvent_t eFork, eJoin;
    cudaEventCreateWithFlags(&eFork, cudaEventDisableTiming);
    cudaEventCreateWithFlags(&eJoin, cudaEventDisableTiming);

    cudaEventRecord(eFork, 0);
    cudaStreamWaitEvent(sb, eFork, 0);
    const int EDGE_GRID = (N_EDGES + 255) / 256;
    hist_gstart_kernel<<<EDGE_GRID, 256, 0, sb>>>(dst, deg, cluster, gstart);
    scan1_kernel<<<NCHUNK, 256, 0, sb>>>(deg, ptrL, part);
    scan2_kernel<<<1, 256, 0, sb>>>(part, offp);
    fill_kernel<<<EDGE_GRID, 256, 0, sb>>>(src, dst, fill, csr);
    cudaEventRecord(eJoin, sb);

    // main stream: combined pack + layer0 GEMM
    pack_all_kernel<<<MT_PAD + 80, 256>>>(x, Wl0, Wr0, Wl1, Wr1, Wl2, Wr2, ah, wh);

    dim3 gg(391, 2);
    f16_gemm<<<gg, 256, SMEM>>>(ah, wh + 0 * 8192, wh + 1 * 8192, yh, zh, N_NODES);

    cudaStreamWaitEvent(0, eJoin, 0);

    // ---- layer 0 aggregation ----
    agg128_pack_kernel<<<AGG_BLOCKS, 256>>>(yh, zh, bl0, csr, ah, nullptr, nullptr);

    // ---- layer 1 ----
    f16_gemm<<<gg, 256, SMEM>>>(ah, wh + 2 * 8192, wh + 3 * 8192, yh, zh, N_NODES);
    agg128_pack_kernel<<<AGG_BLOCKS, 256>>>(yh, zh, bl1, csr, ah, out_pre, x2);

    // ---- layer 2 fused GEMM ([Wl2|Wr2]) ----
    dim3 gg1(391, 1);
    f16_gemm<<<gg1, 256, SMEM>>>(ah, wh + 4 * 8192, wh + 4 * 8192, yh, nullptr, N_NODES);

    // ---- final: log-softmax agg + pooling + scratch re-zero ----
    final_kernel<<<AGG_BLOCKS + 64, 256>>>(yh, bl2, csr, x2, gstart, out_lsm, out_g);
}

// round 17
// speedup vs baseline: 1.4057x; 1.0572x over previous
#include <cuda_runtime.h>
#include <cuda_fp16.h>
#include <math.h>
#include <stdint.h>

#define N_NODES 50000
#define N_EDGES 600000
#define C_HID 128
#define C_OUT 64
#define N_GRAPHS 512
#define MT_PAD 3128     // 391*8 m-tiles of 16 rows
#define NCHUNK 196      // ceil(50000/256)
#define AGG_BLOCKS 6250 // 50000/8 warps

// ---------------- scratch (__device__ globals) -------------------------------
__device__ __half   g_yh[N_NODES * 128];   // y (gathered operand), fp16
__device__ __half   g_zh[N_NODES * 128];   // z (self term), fp16
__device__ uint32_t g_ah[MT_PAD * 8 * 128];  // A operand, fp16x2 fragments
__device__ uint32_t g_wh[5 * 8192];          // weights, fp16x2 fragments
__device__ int      g_deg[N_NODES];      // zeroed at end of each run
__device__ int      g_fill[N_NODES];     // zeroed at end of each run
__device__ int      g_ptrL[N_NODES];
__device__ int      g_off[256];
__device__ int      g_part[256];
__device__ int      g_csr[N_EDGES];
__device__ int      g_gstart[N_GRAPHS + 1];

__device__ __forceinline__ int ptr_at(int i) {
    if (i >= N_NODES) return N_EDGES;
    return g_ptrL[i] + g_off[i >> 8];
}

// ---------------- CSR helpers (int4-vectorized edge loads) -------------------
__global__ void hist_gstart_kernel(const int4* __restrict__ dst4, int* __restrict__ deg,
                                   const int* __restrict__ cluster, int* __restrict__ gstart) {
    int i = blockIdx.x * blockDim.x + threadIdx.x;
    if (i < N_EDGES / 4) {
        int4 d = dst4[i];
        atomicAdd(&deg[d.x], 1);
        atomicAdd(&deg[d.y], 1);
        atomicAdd(&deg[d.z], 1);
        atomicAdd(&deg[d.w], 1);
    }
    if (i <= N_GRAPHS) {
        if (i == N_GRAPHS) gstart[i] = N_NODES;
        else {
            int lo = 0, hi = N_NODES;
            while (lo < hi) {
                int mid = (lo + hi) >> 1;
                if (cluster[mid] < i) lo = mid + 1; else hi = mid;
            }
            gstart[i] = lo;
        }
    }
}

__global__ void scan1_kernel(const int* __restrict__ deg, int* __restrict__ ptrL,
                             int* __restrict__ part) {
    __shared__ int s[256];
    int t = threadIdx.x;
    int i = blockIdx.x * 256 + t;
    int d = (i < N_NODES) ? deg[i] : 0;
    s[t] = d;
    __syncthreads();
#pragma unroll
    for (int off = 1; off < 256; off <<= 1) {
        int v = (t >= off) ? s[t - off] : 0;
        __syncthreads();
        s[t] += v;
        __syncthreads();
    }
    if (i < N_NODES) ptrL[i] = s[t] - d;
    if (t == 255) part[blockIdx.x] = s[255];
}

__global__ void scan2_kernel(const int* __restrict__ part, int* __restrict__ off) {
    __shared__ int s[256];
    int t = threadIdx.x;
    int v0 = (t < NCHUNK) ? part[t] : 0;
    s[t] = v0;
    __syncthreads();
#pragma unroll
    for (int off2 = 1; off2 < 256; off2 <<= 1) {
        int v = (t >= off2) ? s[t - off2] : 0;
        __syncthreads();
        s[t] += v;
        __syncthreads();
    }
    off[t] = s[t] - v0;
}

__global__ void fill_kernel(const int4* __restrict__ src4, const int4* __restrict__ dst4,
                            int* __restrict__ fill, int* __restrict__ csr) {
    int i = blockIdx.x * blockDim.x + threadIdx.x;
    if (i >= N_EDGES / 4) return;
    int4 s = src4[i];
    int4 d = dst4[i];
    csr[g_ptrL[d.x] + g_off[d.x >> 8] + atomicAdd(&fill[d.x], 1)] = s.x;
    csr[g_ptrL[d.y] + g_off[d.y >> 8] + atomicAdd(&fill[d.y], 1)] = s.y;
    csr[g_ptrL[d.z] + g_off[d.z >> 8] + atomicAdd(&fill[d.z], 1)] = s.z;
    csr[g_ptrL[d.w] + g_off[d.w >> 8] + atomicAdd(&fill[d.w], 1)] = s.w;
}

// ---------------- fp16 pack helpers ------------------------------------------
__device__ __forceinline__ uint32_t pack_f16x2(float x, float y) {
    __half2 h = __floats2half2_rn(x, y);
    return *reinterpret_cast<uint32_t*>(&h);
}

// ---- combined packing: blocks [0,MT_PAD) pack A(x) fp16; rest pack weights --
__global__ void pack_all_kernel(const float* __restrict__ A,
                                const float* W0, const float* W1, const float* W2,
                                const float* W3, const float* W4, const float* W5,
                                uint32_t* __restrict__ Ah,
                                uint32_t* __restrict__ Wh) {
    int warp = threadIdx.x >> 5;
    int lane = threadIdx.x & 31;
    int gidl = lane >> 2, tig = lane & 3;

    if (blockIdx.x < MT_PAD) {
        int it = blockIdx.x * 8 + warp;
        int mt = it >> 3, kt = it & 7;
        uint32_t h[4];
#pragma unroll
        for (int r = 0; r < 4; r++) {
            int row = mt * 16 + gidl + (r & 1) * 8;
            int col = kt * 16 + tig * 2 + (r >> 1) * 8;
            float2 v = make_float2(0.f, 0.f);
            if (row < N_NODES) v = *reinterpret_cast<const float2*>(&A[row * 128 + col]);
            h[r] = pack_f16x2(v.x, v.y);
        }
        *reinterpret_cast<uint4*>(&Ah[(it * 32 + lane) * 4]) = make_uint4(h[0], h[1], h[2], h[3]);
        return;
    }

    int wit = (blockIdx.x - MT_PAD) * 8 + warp;
    if (wit >= 640) return;
    const float* W;
    int BNs, dst_mat, nt_off, tile;
    if (wit < 512) {
        int m = wit >> 7;
        tile = wit & 127;
        BNs = 128; dst_mat = m; nt_off = 0;
        W = (m == 0) ? W0 : (m == 1) ? W1 : (m == 2) ? W2 : W3;
    } else {
        int m = (wit - 512) >> 6;
        tile = (wit - 512) & 63;
        BNs = 64; dst_mat = 4; nt_off = m ? 8 : 0;
        W = m ? W5 : W4;
    }
    int NTs = BNs / 8;
    int kt = tile / NTs, nt = tile % NTs;
    int col = nt * 8 + gidl;
    uint32_t h[2];
#pragma unroll
    for (int r = 0; r < 2; r++) {
        int k = kt * 16 + tig * 2 + r * 8;
        float v0 = W[k * BNs + col];
        float v1 = W[(k + 1) * BNs + col];
        h[r] = pack_f16x2(v0, v1);
    }
    int didx = dst_mat * 8192 + (kt * 16 + nt + nt_off) * 64 + lane * 2;
    *reinterpret_cast<uint2*>(&Wh[didx]) = make_uint2(h[0], h[1]);
}

// ---------------- fp16 GEMM ---------------------------------------------------
__device__ __forceinline__ uint32_t smem_u32(const void* p) {
    uint32_t a;
    asm("{ .reg .u64 t; cvta.to.shared.u64 t, %1; cvt.u32.u64 %0, t; }" : "=r"(a) : "l"(p));
    return a;
}

__device__ __forceinline__ void cp16(uint32_t dst, const void* src) {
    asm volatile("cp.async.cg.shared.global [%0], [%1], 16;" :: "r"(dst), "l"(src) : "memory");
}

#define MMA_F16(c, a, b)                                                          \
    asm volatile(                                                                 \
        "mma.sync.aligned.m16n8k16.row.col.f32.f16.f16.f32 "                      \
        "{%0,%1,%2,%3},{%4,%5,%6,%7},{%8,%9},{%0,%1,%2,%3};"                      \
        : "+f"(c[0]), "+f"(c[1]), "+f"(c[2]), "+f"(c[3])                          \
        : "r"(a[0]), "r"(a[1]), "r"(a[2]), "r"(a[3]), "r"(b[0]), "r"(b[1]))

// C = A[M,128] @ W[128,128], pure fp16 operands, fp32 accumulate.
__global__ __launch_bounds__(256, 2) void f16_gemm(
    const uint32_t* __restrict__ Ah,
    const uint32_t* __restrict__ Bh0, const uint32_t* __restrict__ Bh1,
    __half* __restrict__ C0h, __half* __restrict__ C1h, int M) {
    constexpr int NT = 16;
    constexpr int STAGE = 8192 + 8192;
    extern __shared__ char smem[];

    const uint32_t* Bh = blockIdx.y ? Bh1 : Bh0;
    __half* C = blockIdx.y ? C1h : C0h;

    uint32_t sb = smem_u32(smem);
    int tid = threadIdx.x, lane = tid & 31, warp = tid >> 5;
    int wm = warp & 1, wn = warp >> 1;
    int bRow = blockIdx.x * 128;

    float acc[4][4][4];
#pragma unroll
    for (int mt = 0; mt < 4; mt++)
#pragma unroll
        for (int nt = 0; nt < 4; nt++)
#pragma unroll
            for (int j = 0; j < 4; j++) acc[mt][nt][j] = 0.f;

    auto load_stage = [&](int kc, int buf) {
#pragma unroll
        for (int i = 0; i < 2; i++) {   // A: 8KB
            int c = tid + i * 256;
            int t = c >> 5, o = (c & 31) * 16;
            int kt = t >> 3, mt = t & 7;
            const uint32_t* src = Ah + ((blockIdx.x * 8 + mt) * 8 + kc * 2 + kt) * 128;
            cp16(sb + buf * STAGE + t * 512 + o, (const char*)src + o);
        }
#pragma unroll
        for (int i = 0; i < 2; i++) {   // B: 8KB
            int c = tid + i * 256;
            int t = c >> 4, o = (c & 15) * 16;
            int kt = t >> 4;
            int nt = t & 15;
            const uint32_t* src = Bh + ((kc * 2 + kt) * NT + nt) * 64;
            cp16(sb + buf * STAGE + 8192 + t * 256 + o, (const char*)src + o);
        }
        asm volatile("cp.async.commit_group;" ::: "memory");
    };

    auto compute = [&](int buf) {
#pragma unroll
        for (int kt = 0; kt < 2; kt++) {
            uint32_t a[4][4];
#pragma unroll
            for (int mt = 0; mt < 4; mt++) {
                uint32_t ad = sb + buf * STAGE + (kt * 8 + (wm * 4 + mt)) * 512 + lane * 16;
                asm volatile("ld.shared.v4.b32 {%0,%1,%2,%3},[%4];"
                    : "=r"(a[mt][0]), "=r"(a[mt][1]), "=r"(a[mt][2]), "=r"(a[mt][3]) : "r"(ad));
            }
            uint32_t b[4][2];
#pragma unroll
            for (int nt = 0; nt < 4; nt++) {
                uint32_t ad = sb + buf * STAGE + 8192 +
                    (kt * NT + wn * 4 + nt) * 256 + lane * 8;
                asm volatile("ld.shared.v2.b32 {%0,%1},[%2];"
                    : "=r"(b[nt][0]), "=r"(b[nt][1]) : "r"(ad));
            }
#pragma unroll
            for (int mt = 0; mt < 4; mt++)
#pragma unroll
                for (int nt = 0; nt < 4; nt++)
                    MMA_F16(acc[mt][nt], a[mt], b[nt]);
        }
    };

    load_stage(0, 0);
    for (int kc = 0; kc < 4; kc++) {
        if (kc < 3) {
            load_stage(kc + 1, (kc + 1) & 1);
            asm volatile("cp.async.wait_group 1;" ::: "memory");
        } else {
            asm volatile("cp.async.wait_group 0;" ::: "memory");
        }
        __syncthreads();
        compute(kc & 1);
        __syncthreads();
    }

    int gid = lane >> 2, tig = lane & 3;
#pragma unroll
    for (int mt = 0; mt < 4; mt++) {
        int row = bRow + wm * 64 + mt * 16 + gid;
#pragma unroll
        for (int nt = 0; nt < 4; nt++) {
            int col = wn * 32 + nt * 8 + tig * 2;
            if (row < M)
                *reinterpret_cast<__half2*>(&C[row * 128 + col]) =
                    __floats2half2_rn(acc[mt][nt][0], acc[mt][nt][1]);
            if (row + 8 < M)
                *reinterpret_cast<__half2*>(&C[(row + 8) * 128 + col]) =
                    __floats2half2_rn(acc[mt][nt][2], acc[mt][nt][3]);
        }
    }
}

// ------- aggregation: hadd2-pair accumulation, flush to fp32 every 8 edges ---
__global__ void agg128_pack_kernel(const __half* __restrict__ yh, const __half* __restrict__ zh,
                                   const float* __restrict__ bl,
                                   const int* __restrict__ csr,
                                   uint32_t* __restrict__ Ah,
                                   float* __restrict__ out_pre) {
    int node = blockIdx.x * 8 + (threadIdx.x >> 5);
    if (node >= N_NODES) return;
    int lane = threadIdx.x & 31;

    int lo = ptr_at(node), hi = ptr_at(node + 1);
    float4 acc = make_float4(0.f, 0.f, 0.f, 0.f);
    const __half2 hz = __floats2half2_rn(0.f, 0.f);
    int e = lo;
    while (e < hi) {
        int stop = min(e + 8, hi);
        __half2 a0 = hz, a1 = hz;
#pragma unroll 8
        for (; e < stop; e++) {
            int s = csr[e];
            uint2 raw = *reinterpret_cast<const uint2*>(&yh[s * 128 + lane * 4]);
            a0 = __hadd2(a0, *reinterpret_cast<__half2*>(&raw.x));
            a1 = __hadd2(a1, *reinterpret_cast<__half2*>(&raw.y));
        }
        float2 f0 = __half22float2(a0);
        float2 f1 = __half22float2(a1);
        acc.x += f0.x; acc.y += f0.y; acc.z += f1.x; acc.w += f1.y;
    }
    float inv = 1.f / (float)max(hi - lo, 1);
    float4 b = *reinterpret_cast<const float4*>(&bl[lane * 4]);
    uint2 zraw = *reinterpret_cast<const uint2*>(&zh[node * 128 + lane * 4]);
    float2 z0 = __half22float2(*reinterpret_cast<__half2*>(&zraw.x));
    float2 z1 = __half22float2(*reinterpret_cast<__half2*>(&zraw.y));
    float4 h;
    h.x = acc.x * inv + b.x + z0.x;
    h.y = acc.y * inv + b.y + z0.y;
    h.z = acc.z * inv + b.z + z1.x;
    h.w = acc.w * inv + b.w + z1.y;
    if (out_pre) *reinterpret_cast<float4*>(&out_pre[node * 128 + lane * 4]) = h;
    float4 r = make_float4(fmaxf(h.x, 0.f), fmaxf(h.y, 0.f), fmaxf(h.z, 0.f), fmaxf(h.w, 0.f));

    int mt = node >> 4, gid = node & 7, rowhalf = (node >> 3) & 1;
    int kt = lane >> 2;
    float v01[2] = {r.x, r.z};
    float v11[2] = {r.y, r.w};
#pragma unroll
    for (int p = 0; p < 2; p++) {
        int c = lane * 4 + 2 * p;
        int ct = c & 15;
        int tig = (ct & 7) >> 1;
        int colhalf = ct >> 3;
        int reg = rowhalf + 2 * colhalf;
        int idx = ((mt * 8 + kt) * 32 + gid * 4 + tig) * 4 + reg;
        __half2 hh = __floats2half2_rn(v01[p], v11[p]);
        Ah[idx] = *reinterpret_cast<uint32_t*>(&hh);
    }
}

// ------- final: lsm (hadd2 gather) + pool (relu(out_pre)) + scratch re-zero --
__global__ void final_kernel(const __half* __restrict__ yzh,
                             const float* __restrict__ bl,
                             const int* __restrict__ csr,
                             const float* __restrict__ pre,   // out_pre (layer1 pre-relu)
                             const int* __restrict__ gstart,
                             float* __restrict__ out_lsm,
                             float* __restrict__ out_g) {
    int lane = threadIdx.x & 31;
    int warp = threadIdx.x >> 5;

    {
        int gtid = blockIdx.x * blockDim.x + threadIdx.x;
        if (gtid < N_NODES) { g_deg[gtid] = 0; g_fill[gtid] = 0; }
    }

    if (blockIdx.x < AGG_BLOCKS) {
        int node = blockIdx.x * 8 + warp;
        if (node >= N_NODES) return;
        int lo = ptr_at(node), hi = ptr_at(node + 1);
        float2 acc = make_float2(0.f, 0.f);
        const __half2 hz = __floats2half2_rn(0.f, 0.f);
        int e = lo;
        while (e < hi) {
            int stop = min(e + 8, hi);
            __half2 a0 = hz;
#pragma unroll 8
            for (; e < stop; e++) {
                int s = csr[e];
                a0 = __hadd2(a0, *reinterpret_cast<const __half2*>(&yzh[s * 128 + lane * 2]));
            }
            float2 f = __half22float2(a0);
            acc.x += f.x; acc.y += f.y;
        }
        float inv = 1.f / (float)max(hi - lo, 1);
        float2 b = *reinterpret_cast<const float2*>(&bl[lane * 2]);
        __half2 zv = *reinterpret_cast<const __half2*>(&yzh[node * 128 + 64 + lane * 2]);
        float2 zi = __half22float2(zv);
        float2 h;
        h.x = acc.x * inv + b.x + zi.x;
        h.y = acc.y * inv + b.y + zi.y;

        float m = fmaxf(h.x, h.y);
#pragma unroll
        for (int off = 16; off > 0; off >>= 1)
            m = fmaxf(m, __shfl_xor_sync(0xFFFFFFFFu, m, off));
        float s = expf(h.x - m) + expf(h.y - m);
#pragma unroll
        for (int off = 16; off > 0; off >>= 1)
            s += __shfl_xor_sync(0xFFFFFFFFu, s, off);
        float ls = logf(s);
        *reinterpret_cast<float2*>(&out_lsm[node * 64 + lane * 2]) =
            make_float2(h.x - m - ls, h.y - m - ls);
    } else {
        int g = (blockIdx.x - AGG_BLOCKS) * 8 + warp;
        if (g >= N_GRAPHS) return;
        int lo = gstart[g], hi = gstart[g + 1];
        float4 acc = make_float4(0.f, 0.f, 0.f, 0.f);
        for (int i = lo; i < hi; i++) {
            float4 v = *reinterpret_cast<const float4*>(&pre[i * 128 + lane * 4]);
            acc.x += fmaxf(v.x, 0.f);
            acc.y += fmaxf(v.y, 0.f);
            acc.z += fmaxf(v.z, 0.f);
            acc.w += fmaxf(v.w, 0.f);
        }
        float inv = 1.f / (float)max(hi - lo, 1);
        acc.x *= inv; acc.y *= inv; acc.z *= inv; acc.w *= inv;
        *reinterpret_cast<float4*>(&out_g[g * 128 + lane * 4]) = acc;
    }
}

// ---------------- launch -----------------------------------------------------
extern "C" void kernel_launch(void* const* d_in, const int* in_sizes, int n_in,
                              void* d_out, int out_size) {
    const float* x       = (const float*)d_in[0];
    const int*   ei      = (const int*)d_in[1];
    const int*   cluster = (const int*)d_in[2];
    const float* Wl0 = (const float*)d_in[3];
    const float* bl0 = (const float*)d_in[4];
    const float* Wr0 = (const float*)d_in[5];
    const float* Wl1 = (const float*)d_in[6];
    const float* bl1 = (const float*)d_in[7];
    const float* Wr1 = (const float*)d_in[8];
    const float* Wl2 = (const float*)d_in[9];
    const float* bl2 = (const float*)d_in[10];
    const float* Wr2 = (const float*)d_in[11];

    const int* src = ei;
    const int* dst = ei + N_EDGES;

    float* out = (float*)d_out;
    float* out_lsm = out;
    float* out_pre = out + N_NODES * C_OUT;
    float* out_g   = out + N_NODES * C_OUT + N_NODES * C_HID;

    __half *yh, *zh;
    uint32_t *ah, *wh;
    int *deg, *fill, *csr, *gstart;
    cudaGetSymbolAddress((void**)&yh, g_yh);
    cudaGetSymbolAddress((void**)&zh, g_zh);
    cudaGetSymbolAddress((void**)&ah, g_ah);
    cudaGetSymbolAddress((void**)&wh, g_wh);
    cudaGetSymbolAddress((void**)&deg, g_deg);
    cudaGetSymbolAddress((void**)&fill, g_fill);
    cudaGetSymbolAddress((void**)&csr, g_csr);
    cudaGetSymbolAddress((void**)&gstart, g_gstart);

    int *ptrL, *offp, *part;
    cudaGetSymbolAddress((void**)&ptrL, g_ptrL);
    cudaGetSymbolAddress((void**)&offp, g_off);
    cudaGetSymbolAddress((void**)&part, g_part);

    const int SMEM = 2 * (8192 + 8192);  // 32768
    cudaFuncSetAttribute(f16_gemm, cudaFuncAttributeMaxDynamicSharedMemorySize, SMEM);

    // ---- fork: CSR build on side stream (deg/fill pre-zeroed by prior run) ----
    cudaStream_t sb;
    cudaStreamCreateWithFlags(&sb, cudaStreamNonBlocking);
    cudaEvent_t eFork, eJoin;
    cudaEventCreateWithFlags(&eFork, cudaEventDisableTiming);
    cudaEventCreateWithFlags(&eJoin, cudaEventDisableTiming);

    cudaEventRecord(eFork, 0);
    cudaStreamWaitEvent(sb, eFork, 0);
    const int EDGE4_GRID = (N_EDGES / 4 + 255) / 256;  // 586
    hist_gstart_kernel<<<EDGE4_GRID, 256, 0, sb>>>((const int4*)dst, deg, cluster, gstart);
    scan1_kernel<<<NCHUNK, 256, 0, sb>>>(deg, ptrL, part);
    scan2_kernel<<<1, 256, 0, sb>>>(part, offp);
    fill_kernel<<<EDGE4_GRID, 256, 0, sb>>>((const int4*)src, (const int4*)dst, fill, csr);
    cudaEventRecord(eJoin, sb);

    // main stream: combined pack + layer0 GEMM
    pack_all_kernel<<<MT_PAD + 80, 256>>>(x, Wl0, Wr0, Wl1, Wr1, Wl2, Wr2, ah, wh);

    dim3 gg(391, 2);
    f16_gemm<<<gg, 256, SMEM>>>(ah, wh + 0 * 8192, wh + 1 * 8192, yh, zh, N_NODES);

    cudaStreamWaitEvent(0, eJoin, 0);

    // ---- layer 0 aggregation ----
    agg128_pack_kernel<<<AGG_BLOCKS, 256>>>(yh, zh, bl0, csr, ah, nullptr);

    // ---- layer 1 ----
    f16_gemm<<<gg, 256, SMEM>>>(ah, wh + 2 * 8192, wh + 3 * 8192, yh, zh, N_NODES);
    agg128_pack_kernel<<<AGG_BLOCKS, 256>>>(yh, zh, bl1, csr, ah, out_pre);

    // ---- layer 2 fused GEMM ([Wl2|Wr2]) ----
    dim3 gg1(391, 1);
    f16_gemm<<<gg1, 256, SMEM>>>(ah, wh + 4 * 8192, wh + 4 * 8192, yh, nullptr, N_NODES);

    // ---- final: log-softmax agg + pooling (relu of out_pre) + scratch re-zero ----
    final_kernel<<<AGG_BLOCKS + 64, 256>>>(yh, bl2, csr, out_pre, gstart, out_lsm, out_g);
}